// round 12
// baseline (speedup 1.0000x reference)
#include <cuda_runtime.h>
#include <cuda_fp16.h>
#include <math.h>
#include <float.h>

#define BN 8
#define H 480
#define W 640
#define OH 120
#define OW 160
#define CH 128
#define NP 192

typedef unsigned long long u64;
typedef unsigned int u32;

// ---------------- scratch ----------------
__device__ float d_cellval[BN*256];
__device__ int   d_cellxy[BN*256];
__device__ int   d_selxy[BN*NP];
// channel-last fmap copy: [b][oy][ox][ch]
__device__ __align__(16) float d_cl[(size_t)BN*OH*OW*CH];
// fp16 hi/lo split weights, padded [128 ch][72 taps] as u32 pairs [128][36]
__device__ u32 d_wAhi32[128*36];
__device__ u32 d_wAlo32[128*36];

// ---------------- helpers ----------------
__device__ __forceinline__ unsigned smem_u32(const void* p) {
    unsigned a;
    asm("{ .reg .u64 t; cvta.to.shared.u64 t, %1; cvt.u32.u64 %0, t; }" : "=r"(a) : "l"(p));
    return a;
}
#define LDM_X4(r0,r1,r2,r3,addr) \
    asm volatile("ldmatrix.sync.aligned.m8n8.x4.shared.b16 {%0,%1,%2,%3}, [%4];" \
        : "=r"(r0),"=r"(r1),"=r"(r2),"=r"(r3) : "r"(addr))
#define LDM_X2(r0,r1,addr) \
    asm volatile("ldmatrix.sync.aligned.m8n8.x2.shared.b16 {%0,%1}, [%2];" \
        : "=r"(r0),"=r"(r1) : "r"(addr))
#define MMA16816F16(d, a0,a1,a2,a3, b0,b1) \
    asm volatile("mma.sync.aligned.m16n8k16.row.col.f32.f16.f16.f32 " \
        "{%0,%1,%2,%3}, {%4,%5,%6,%7}, {%8,%9}, {%0,%1,%2,%3};" \
        : "+f"((d)[0]),"+f"((d)[1]),"+f"((d)[2]),"+f"((d)[3]) \
        : "r"(a0),"r"(a1),"r"(a2),"r"(a3),"r"(b0),"r"(b1))

__device__ __forceinline__ u32 pack_h2(float v0, float v1) {
    __half2 h2 = __floats2half2_rn(v0, v1);
    return *(u32*)&h2;
}

// ================= K0: weight prep — fp16 hi/lo split, padded [128][72] =========
__global__ void k_wprep(const float* __restrict__ wf) {
    int i = blockIdx.x * blockDim.x + threadIdx.x;   // 128*36
    if (i >= 128*36) return;
    int ch = i / 36, j = i - ch*36;
    int t0 = 2*j, t1 = 2*j + 1;
    float v0 = (t0 < 49) ? __ldg(wf + ch*49 + t0) : 0.f;
    float v1 = (t1 < 49) ? __ldg(wf + ch*49 + t1) : 0.f;
    __half h0 = __float2half_rn(v0), h1 = __float2half_rn(v1);
    d_wAhi32[i] = pack_h2(__half2float(h0), __half2float(h1));
    d_wAlo32[i] = pack_h2(v0 - __half2float(h0), v1 - __half2float(h1));
}

// ================= K1: fused harris + per-cell argmax =================
__global__ __launch_bounds__(256) void k_harris(const float* __restrict__ frame) {
    __shared__ float sf[37][48];
    __shared__ float shxx[36][40], shyy[36][40], shxy[36][40];
    __shared__ float sv[256];
    __shared__ int   si[256];

    int blk = blockIdx.x;
    int b = blk >> 8, cell = blk & 255;
    int gh = cell >> 4, gw = cell & 15;
    int gx0 = gw * 40, gy0 = gh * 30;
    int X0 = gx0 - 3, Y0 = gy0 - 3;
    const float* f = frame + (size_t)b * H * W;
    int tid = threadIdx.x;

    for (int i = tid; i < 37 * 47; i += 256) {
        int r = i / 47, c = i - r * 47;
        int x = X0 + c, y = Y0 + r;
        sf[r][c] = (x >= 0 && x < W && y >= 0 && y < H) ? f[y * W + x] : 0.f;
    }
    __syncthreads();

    for (int i = tid; i < 36 * 40; i += 256) {
        int r = i / 40, c = i - r * 40;
        int y = Y0 + r;
        float a = 0.f, bb = 0.f, cc2 = 0.f;
        if (y >= 0 && y < H) {
            bool ylast = (y == H - 1);
            #pragma unroll
            for (int k = 0; k < 7; k++) {
                int cw = c + k;
                int x = X0 + cw;
                if (x >= 0 && x < W) {
                    float dx = (x < W - 1) ? (sf[r][cw+1] - sf[r][cw])
                                           : (sf[r][cw-1] - sf[r][cw-2]);
                    float dy = !ylast ? (sf[r+1][cw] - sf[r][cw])
                                      : (sf[r-1][cw] - sf[r-2][cw]);
                    a   = fmaf(dx, dx, a);
                    bb  = fmaf(dy, dy, bb);
                    cc2 = fmaf(dx, dy, cc2);
                }
            }
        }
        shxx[r][c] = a; shyy[r][c] = bb; shxy[r][c] = cc2;
    }
    __syncthreads();

    float bv = -FLT_MAX;
    int   bi = 0x7FFFFFFF;
    for (int fi = tid; fi < 1200; fi += 256) {
        int py = fi / 40, px = fi - py * 40;
        float a = 0.f, bb = 0.f, cc = 0.f;
        #pragma unroll
        for (int k = 0; k < 7; k++) {
            a  += shxx[py + k][px];
            bb += shyy[py + k][px];
            cc += shxy[py + k][px];
        }
        float Ixx = a / 49.0f, Iyy = bb / 49.0f, Ixy = cc / 49.0f;
        float g = (Ixx * Iyy - Ixy * Ixy) / (Ixx + Iyy + 1e-8f);
        if (g > bv) { bv = g; bi = fi; }
    }
    sv[tid] = bv; si[tid] = bi;
    __syncthreads();
    for (int s = 128; s > 0; s >>= 1) {
        if (tid < s) {
            float v2 = sv[tid + s]; int i2 = si[tid + s];
            if (v2 > sv[tid] || (v2 == sv[tid] && i2 < si[tid])) { sv[tid] = v2; si[tid] = i2; }
        }
        __syncthreads();
    }
    if (tid == 0) {
        int fi = si[0];
        int py = fi / 40, px = fi - py * 40;
        d_cellval[blk] = sv[0];
        d_cellxy[blk]  = ((gy0 + py) << 16) | (gx0 + px);
    }
}

// ================= K2: top-192 by rank count (stable) =================
__global__ void k_topk(float* __restrict__ out_coords) {
    __shared__ float sv[256];
    __shared__ int   sxy[256];
    int b = blockIdx.x, i = threadIdx.x;
    sv[i]  = d_cellval[b*256 + i];
    sxy[i] = d_cellxy[b*256 + i];
    __syncthreads();
    float v = sv[i];
    int rank = 0;
    #pragma unroll 8
    for (int j = 0; j < 256; j++) {
        float vj = sv[j];
        rank += (vj > v) || (vj == v && j < i);
    }
    if (rank < NP) {
        int xy = sxy[i];
        int x = xy & 0xFFFF, y = xy >> 16;
        out_coords[((size_t)b*NP + rank)*2 + 0] = (float)x;
        out_coords[((size_t)b*NP + rank)*2 + 1] = (float)y;
        d_selxy[b*NP + rank] = xy;
    }
}

// ================= K3: conv v12 — mma.sync fp16, 2-term w-split ==================
// CTA: 256 thr = 8 warps, tile 4 oy x 32 ox = 128 px, all 128 ch.
// D = (Wh + Wl) . Xh^T: 2 GEMM terms, K padded 49->64, fp32 accum.
#define BSTRIDE 72                       // fp16 per row (144 B, 36 words)
#define OFF_A_HI  0
#define OFF_A_LO  18432
#define OFF_B     36864
#define OFF_IN    55296                  // float[19*132] = 10032 B
#define SMEM_TOT  67648                  // stage overlay: 128 px x 132 floats
#define STG_STRIDE 132

__global__ __launch_bounds__(256) void k_conv_tc(
    const float* __restrict__ frame,
    const float* __restrict__ bf,
    float* __restrict__ fmap)
{
    extern __shared__ __align__(16) unsigned char smem[];
    unsigned sbase = smem_u32(smem);
    float* s_in = (float*)(smem + OFF_IN);

    int tid  = threadIdx.x;
    int lane = tid & 31;
    int warp = tid >> 5;

    int ox0 = blockIdx.x * 32;
    int oy0 = blockIdx.y * 4;
    int b   = blockIdx.z;
    const float* f = frame + (size_t)b * H * W;

    // ---- prologue: weights (coalesced u32 copy) + input window ----
    {
        u32* aH = (u32*)(smem + OFF_A_HI);
        u32* aL = (u32*)(smem + OFF_A_LO);
        for (int i = tid; i < 128*36; i += 256) { aH[i] = d_wAhi32[i]; aL[i] = d_wAlo32[i]; }
        int row0 = oy0 * 4 - 3, col0 = ox0 * 4 - 3;
        for (int i = tid; i < 19 * 131; i += 256) {
            int r = i / 131, c = i - r * 131;
            int y = row0 + r, x = col0 + c;
            s_in[r * 132 + c] = (y >= 0 && y < H && x >= 0 && x < W) ? f[(size_t)y * W + x] : 0.f;
        }
    }
    __syncthreads();

    // ---- im2col: thread = px (tid < 128); fp16 pairs, packed u32 writes ----
    if (tid < 128) {
        int oyr = tid >> 5, oxl = tid & 31;
        u32* bB = (u32*)(smem + OFF_B) + tid * 36;
        const float* base = s_in + oyr * 4 * 132 + oxl * 4;
        #pragma unroll
        for (int j = 0; j < 36; j++) {
            int t0 = 2*j, t1 = 2*j + 1;
            float v0 = 0.f, v1 = 0.f;
            if (t0 < 49) v0 = base[(t0/7) * 132 + (t0%7)];
            if (t1 < 49) v1 = base[(t1/7) * 132 + (t1%7)];
            bB[j] = pack_h2(v0, v1);
        }
    }
    __syncthreads();

    // ---- MMA main loop: ks outer, B frags shared across 2 terms ----
    int wm = warp & 3, wn = warp >> 2;
    int m0 = wm * 32;
    int n0 = wn * 64;
    float acc[2][8][4];
    #pragma unroll
    for (int mi = 0; mi < 2; mi++)
        #pragma unroll
        for (int ni = 0; ni < 8; ni++)
            #pragma unroll
            for (int r = 0; r < 4; r++) acc[mi][ni][r] = 0.f;

    unsigned aRowOff = ((lane & 15) * BSTRIDE + ((lane >> 4) << 3)) * 2;
    unsigned bRowOff = ((lane & 7)  * BSTRIDE + (((lane >> 3) & 1) << 3)) * 2;
    unsigned aHiBase = sbase + OFF_A_HI + m0 * (BSTRIDE*2) + aRowOff;
    unsigned aLoBase = sbase + OFF_A_LO + m0 * (BSTRIDE*2) + aRowOff;
    unsigned bBase   = sbase + OFF_B    + n0 * (BSTRIDE*2) + bRowOff;

    #pragma unroll
    for (int ks = 0; ks < 4; ks++) {
        unsigned kb = ks * 32;                  // 16 fp16 = 32 bytes
        u32 bb[8][2];
        #pragma unroll
        for (int ni = 0; ni < 8; ni++)
            LDM_X2(bb[ni][0], bb[ni][1], bBase + ni * 8 * (BSTRIDE*2) + kb);
        // term hi
        {
            u32 a0,a1,a2,a3, a4,a5,a6,a7;
            LDM_X4(a0,a1,a2,a3, aHiBase + kb);
            LDM_X4(a4,a5,a6,a7, aHiBase + 16*(BSTRIDE*2) + kb);
            #pragma unroll
            for (int ni = 0; ni < 8; ni++) {
                MMA16816F16(acc[0][ni], a0,a1,a2,a3, bb[ni][0],bb[ni][1]);
                MMA16816F16(acc[1][ni], a4,a5,a6,a7, bb[ni][0],bb[ni][1]);
            }
        }
        // term lo
        {
            u32 a0,a1,a2,a3, a4,a5,a6,a7;
            LDM_X4(a0,a1,a2,a3, aLoBase + kb);
            LDM_X4(a4,a5,a6,a7, aLoBase + 16*(BSTRIDE*2) + kb);
            #pragma unroll
            for (int ni = 0; ni < 8; ni++) {
                MMA16816F16(acc[0][ni], a0,a1,a2,a3, bb[ni][0],bb[ni][1]);
                MMA16816F16(acc[1][ni], a4,a5,a6,a7, bb[ni][0],bb[ni][1]);
            }
        }
    }
    __syncthreads();   // A/B/IN dead; stage overlays them

    // ---- epilogue: bias + relu -> conflict-free stage -> coalesced copy-out ----
    float* stg = (float*)smem;           // [px][132]
    int l4 = lane >> 2, l2 = (lane & 3) * 2;
    #pragma unroll
    for (int mi = 0; mi < 2; mi++) {
        int ch0 = m0 + mi*16 + l4;
        float bv0 = __ldg(bf + ch0);
        float bv1 = __ldg(bf + ch0 + 8);
        #pragma unroll
        for (int ni = 0; ni < 8; ni++) {
            int px = n0 + ni*8 + l2;
            stg[ px    * STG_STRIDE + ch0    ] = fmaxf(acc[mi][ni][0] + bv0, 0.f);
            stg[(px+1) * STG_STRIDE + ch0    ] = fmaxf(acc[mi][ni][1] + bv0, 0.f);
            stg[ px    * STG_STRIDE + ch0 + 8] = fmaxf(acc[mi][ni][2] + bv1, 0.f);
            stg[(px+1) * STG_STRIDE + ch0 + 8] = fmaxf(acc[mi][ni][3] + bv1, 0.f);
        }
    }
    __syncthreads();

    // fmap: [b][ch][oy][ox] — lanes = ox (coalesced 128B)
    for (int i = tid; i < 128 * 128; i += 256) {
        int px = i & 127, ch = i >> 7;
        int oy = oy0 + (px >> 5), ox = ox0 + (px & 31);
        fmap[(((size_t)(b*CH + ch))*OH + oy)*OW + ox] = stg[px * STG_STRIDE + ch];
    }
    // d_cl: [b][oy][ox][ch] — float4, coalesced 512B per warp
    for (int i = tid; i < 128 * 32; i += 256) {
        int px = i >> 5, c4 = (i & 31) * 4;
        float4 v = *(const float4*)(stg + px * STG_STRIDE + c4);
        int oy = oy0 + (px >> 5), ox = ox0 + (px & 31);
        *(float4*)(d_cl + (((size_t)(b*OH + oy))*OW + ox)*CH + c4) = v;
    }
}

// ================= K4: patches_f — channel-last coalesced gather =============
__global__ __launch_bounds__(128) void k_patches_f(float* __restrict__ out) {
    __shared__ float s[CH * 49];
    int bp = blockIdx.x;
    int b  = bp / NP;
    int c  = threadIdx.x;
    int xy = d_selxy[bp];
    float fx = (float)(xy & 0xFFFF) * 0.25f;
    float fy = (float)(xy >> 16)    * 0.25f;
    int x0 = (int)floorf(fx);
    int y0 = (int)floorf(fy);
    float wx = fx - (float)x0, wy = fy - (float)y0;
    int gx0 = x0 - 3, gy0 = y0 - 3;

    const float* base = d_cl + (size_t)b * OH * OW * CH + c;

    float v[64];
    #pragma unroll
    for (int pt = 0; pt < 64; pt++) {
        int yy = pt >> 3, xx = pt & 7;
        int gy = gy0 + yy, gx = gx0 + xx;
        bool ok = (gx >= 0) & (gx < OW) & (gy >= 0) & (gy < OH);
        v[pt] = ok ? __ldg(base + ((size_t)gy * OW + gx) * CH) : 0.f;
    }

    float w00 = (1.f - wx) * (1.f - wy);
    float w10 = wx * (1.f - wy);
    float w01 = (1.f - wx) * wy;
    float w11 = wx * wy;

    #pragma unroll
    for (int j = 0; j < 7; j++) {
        #pragma unroll
        for (int i = 0; i < 7; i++) {
            float acc = v[j*8 + i]       * w00
                      + v[j*8 + i + 1]   * w10
                      + v[(j+1)*8 + i]   * w01
                      + v[(j+1)*8 + i+1] * w11;
            s[c * 49 + (j*7 + i)] = acc;
        }
    }
    __syncthreads();

    float* o = out + (size_t)bp * (CH * 49);
    for (int k = threadIdx.x; k < CH * 49; k += 128)
        o[k] = s[k];
}

// ================= K5: patches_c — smem-staged weights =================
__global__ __launch_bounds__(128) void k_patches_c(
    const float* __restrict__ frame,
    const float* __restrict__ wc,
    const float* __restrict__ bc,
    float* __restrict__ out)
{
    __shared__ float s_w[CH * 49];
    __shared__ float s_in2[121];
    int bp = blockIdx.x;
    int b  = bp / NP;
    int c  = threadIdx.x;
    int xy = d_selxy[bp];
    float fx = (float)(xy & 0xFFFF) * 0.25f;
    float fy = (float)(xy >> 16)    * 0.25f;
    int x0 = (int)floorf(fx);
    int y0 = (int)floorf(fy);
    float wx = fx - (float)x0, wy = fy - (float)y0;

    const float* f = frame + (size_t)b * H * W;
    int row0 = y0 * 4 - 3, col0 = x0 * 4 - 3;
    for (int i = threadIdx.x; i < CH * 49; i += 128) s_w[i] = __ldg(wc + i);
    for (int i = threadIdx.x; i < 121; i += 128) {
        int r = i / 11, cc = i - r * 11;
        int yyy = row0 + r, xxx = col0 + cc;
        s_in2[i] = (yyy >= 0 && yyy < H && xxx >= 0 && xxx < W) ? f[yyy*W + xxx] : 0.f;
    }
    float bias = __ldg(bc + c);
    __syncthreads();

    float wreg[49];
    #pragma unroll
    for (int i = 0; i < 49; i++) wreg[i] = s_w[c*49 + i];

    float wts[4] = { (1.f-wx)*(1.f-wy), wx*(1.f-wy), (1.f-wx)*wy, wx*wy };
    float acc = 0.f;
    #pragma unroll
    for (int n = 0; n < 4; n++) {
        int dxn = n & 1, dyn = n >> 1;
        int xi = x0 + dxn, yi = y0 + dyn;
        if (xi < OW && yi < OH) {
            float v = bias;
            #pragma unroll
            for (int ky = 0; ky < 7; ky++)
                #pragma unroll
                for (int kx = 0; kx < 7; kx++)
                    v = fmaf(s_in2[(dyn*4 + ky)*11 + (dxn*4 + kx)], wreg[ky*7 + kx], v);
            v = fmaxf(v, 0.f);
            acc += v * wts[n];
        }
    }
    out[(size_t)bp * CH + c] = acc;
}

// ---------------- launch: fork-join; conv placed 4th for ncu slot ---------------
extern "C" void kernel_launch(void* const* d_in, const int* in_sizes, int n_in,
                              void* d_out, int out_size) {
    const float* frame = (const float*)d_in[0];
    const float* w_f   = (const float*)d_in[1];
    const float* b_f   = (const float*)d_in[2];
    const float* w_c   = (const float*)d_in[3];
    const float* b_c   = (const float*)d_in[4];

    float* out        = (float*)d_out;
    float* out_coords = out;                                   // 8*192*2
    float* out_pf     = out + 3072;                            // 8*192*128*49
    float* out_pc     = out + 3072 + 9633792;                  // 8*192*128
    float* out_fmap   = out + 3072 + 9633792 + 196608;         // 8*128*120*160

    static cudaStream_t s1 = 0;
    static cudaEvent_t e_fork = 0, e_topk = 0, e_side = 0;
    if (!s1) {
        cudaStreamCreateWithFlags(&s1, cudaStreamNonBlocking);
        cudaEventCreateWithFlags(&e_fork, cudaEventDisableTiming);
        cudaEventCreateWithFlags(&e_topk, cudaEventDisableTiming);
        cudaEventCreateWithFlags(&e_side, cudaEventDisableTiming);
        cudaFuncSetAttribute(k_conv_tc, cudaFuncAttributeMaxDynamicSharedMemorySize, SMEM_TOT);
    }

    // fork
    cudaEventRecord(e_fork, 0);
    cudaStreamWaitEvent(s1, e_fork, 0);

    // side stream part 1: harris -> topk
    k_harris<<<BN*256, 256, 0, s1>>>(frame);        // launch 1
    k_topk  <<<BN, 256, 0, s1>>>(out_coords);       // launch 2
    cudaEventRecord(e_topk, s1);

    // main stream: wprep -> conv (conv = 4th launch for the ncu -s window)
    k_wprep<<<36, 128>>>(w_f);                      // launch 3
    dim3 gconv(OW/32, OH/4, BN);
    k_conv_tc<<<gconv, 256, SMEM_TOT>>>(frame, b_f, out_fmap);   // launch 4

    // side stream part 2: patches_c (in-order after topk on s1)
    k_patches_c<<<BN*NP, 128, 0, s1>>>(frame, w_c, b_c, out_pc); // launch 5
    cudaEventRecord(e_side, s1);

    // main stream: patches_f (needs conv output AND topk coords)
    cudaStreamWaitEvent(0, e_topk, 0);
    k_patches_f<<<BN*NP, 128>>>(out_pf);            // launch 6

    // join
    cudaStreamWaitEvent(0, e_side, 0);
}

// round 13
// speedup vs baseline: 1.3392x; 1.3392x over previous
#include <cuda_runtime.h>
#include <cuda_fp16.h>
#include <math.h>
#include <float.h>

#define BN 8
#define H 480
#define W 640
#define OH 120
#define OW 160
#define CH 128
#define NP 192

typedef unsigned long long u64;
typedef unsigned int u32;

// ---------------- scratch ----------------
__device__ float d_cellval[BN*256];
__device__ int   d_cellxy[BN*256];
__device__ int   d_selxy[BN*NP];
// channel-last fmap copy: [b][oy][ox][ch]
__device__ __align__(16) float d_cl[(size_t)BN*OH*OW*CH];

// ---------------- helpers ----------------
__device__ __forceinline__ unsigned smem_u32(const void* p) {
    unsigned a;
    asm("{ .reg .u64 t; cvta.to.shared.u64 t, %1; cvt.u32.u64 %0, t; }" : "=r"(a) : "l"(p));
    return a;
}
#define LDM_X4(r0,r1,r2,r3,addr) \
    asm volatile("ldmatrix.sync.aligned.m8n8.x4.shared.b16 {%0,%1,%2,%3}, [%4];" \
        : "=r"(r0),"=r"(r1),"=r"(r2),"=r"(r3) : "r"(addr))
#define MMA16816F16(d, a0,a1,a2,a3, b0,b1) \
    asm volatile("mma.sync.aligned.m16n8k16.row.col.f32.f16.f16.f32 " \
        "{%0,%1,%2,%3}, {%4,%5,%6,%7}, {%8,%9}, {%0,%1,%2,%3};" \
        : "+f"((d)[0]),"+f"((d)[1]),"+f"((d)[2]),"+f"((d)[3]) \
        : "r"(a0),"r"(a1),"r"(a2),"r"(a3),"r"(b0),"r"(b1))

__device__ __forceinline__ u32 pack_h2(float v0, float v1) {
    __half2 h2 = __floats2half2_rn(v0, v1);
    return *(u32*)&h2;
}

// ================= K1: fused harris + per-cell argmax =================
__global__ __launch_bounds__(256) void k_harris(const float* __restrict__ frame) {
    __shared__ float sf[37][48];
    __shared__ float shxx[36][40], shyy[36][40], shxy[36][40];
    __shared__ float sv[256];
    __shared__ int   si[256];

    int blk = blockIdx.x;
    int b = blk >> 8, cell = blk & 255;
    int gh = cell >> 4, gw = cell & 15;
    int gx0 = gw * 40, gy0 = gh * 30;
    int X0 = gx0 - 3, Y0 = gy0 - 3;
    const float* f = frame + (size_t)b * H * W;
    int tid = threadIdx.x;

    for (int i = tid; i < 37 * 47; i += 256) {
        int r = i / 47, c = i - r * 47;
        int x = X0 + c, y = Y0 + r;
        sf[r][c] = (x >= 0 && x < W && y >= 0 && y < H) ? f[y * W + x] : 0.f;
    }
    __syncthreads();

    for (int i = tid; i < 36 * 40; i += 256) {
        int r = i / 40, c = i - r * 40;
        int y = Y0 + r;
        float a = 0.f, bb = 0.f, cc2 = 0.f;
        if (y >= 0 && y < H) {
            bool ylast = (y == H - 1);
            #pragma unroll
            for (int k = 0; k < 7; k++) {
                int cw = c + k;
                int x = X0 + cw;
                if (x >= 0 && x < W) {
                    float dx = (x < W - 1) ? (sf[r][cw+1] - sf[r][cw])
                                           : (sf[r][cw-1] - sf[r][cw-2]);
                    float dy = !ylast ? (sf[r+1][cw] - sf[r][cw])
                                      : (sf[r-1][cw] - sf[r-2][cw]);
                    a   = fmaf(dx, dx, a);
                    bb  = fmaf(dy, dy, bb);
                    cc2 = fmaf(dx, dy, cc2);
                }
            }
        }
        shxx[r][c] = a; shyy[r][c] = bb; shxy[r][c] = cc2;
    }
    __syncthreads();

    float bv = -FLT_MAX;
    int   bi = 0x7FFFFFFF;
    for (int fi = tid; fi < 1200; fi += 256) {
        int py = fi / 40, px = fi - py * 40;
        float a = 0.f, bb = 0.f, cc = 0.f;
        #pragma unroll
        for (int k = 0; k < 7; k++) {
            a  += shxx[py + k][px];
            bb += shyy[py + k][px];
            cc += shxy[py + k][px];
        }
        float Ixx = a / 49.0f, Iyy = bb / 49.0f, Ixy = cc / 49.0f;
        float g = (Ixx * Iyy - Ixy * Ixy) / (Ixx + Iyy + 1e-8f);
        if (g > bv) { bv = g; bi = fi; }
    }
    sv[tid] = bv; si[tid] = bi;
    __syncthreads();
    for (int s = 128; s > 0; s >>= 1) {
        if (tid < s) {
            float v2 = sv[tid + s]; int i2 = si[tid + s];
            if (v2 > sv[tid] || (v2 == sv[tid] && i2 < si[tid])) { sv[tid] = v2; si[tid] = i2; }
        }
        __syncthreads();
    }
    if (tid == 0) {
        int fi = si[0];
        int py = fi / 40, px = fi - py * 40;
        d_cellval[blk] = sv[0];
        d_cellxy[blk]  = ((gy0 + py) << 16) | (gx0 + px);
    }
}

// ================= K2: top-192 by rank count (stable) =================
__global__ void k_topk(float* __restrict__ out_coords) {
    __shared__ float sv[256];
    __shared__ int   sxy[256];
    int b = blockIdx.x, i = threadIdx.x;
    sv[i]  = d_cellval[b*256 + i];
    sxy[i] = d_cellxy[b*256 + i];
    __syncthreads();
    float v = sv[i];
    int rank = 0;
    #pragma unroll 8
    for (int j = 0; j < 256; j++) {
        float vj = sv[j];
        rank += (vj > v) || (vj == v && j < i);
    }
    if (rank < NP) {
        int xy = sxy[i];
        int x = xy & 0xFFFF, y = xy >> 16;
        out_coords[((size_t)b*NP + rank)*2 + 0] = (float)x;
        out_coords[((size_t)b*NP + rank)*2 + 1] = (float)y;
        d_selxy[b*NP + rank] = xy;
    }
}

// ================= K3: conv v13 — mma.sync fp16, 64-px tiles, 2 blocks/SM =======
// CTA: 256 thr = 8 warps, tile 2 oy x 32 ox = 64 px, 128 ch. Warp: 16 ch x 64 px.
// D = (Wh + Wl) . Xh^T, K padded 49->64, fp32 accum. Weights converted in-block.
#define BSTRIDE 72                       // fp16 per row (144 B)
#define OFF_A_HI  0
#define OFF_A_LO  18432
#define OFF_B     36864                  // 64 rows x 144 B = 9216
#define OFF_IN    46080                  // float[11*132] = 5808 B
#define SMEM_TOT  51904
#define STG_STRIDE 132                   // stage overlays A: 64 px x 132 fl = 33792 B

__global__ __launch_bounds__(256, 2) void k_conv_tc(
    const float* __restrict__ frame,
    const float* __restrict__ wf,
    const float* __restrict__ bf,
    float* __restrict__ fmap)
{
    extern __shared__ __align__(16) unsigned char smem[];
    unsigned sbase = smem_u32(smem);
    float* s_in = (float*)(smem + OFF_IN);

    int tid  = threadIdx.x;
    int lane = tid & 31;
    int warp = tid >> 5;

    int ox0 = blockIdx.x * 32;
    int oy0 = blockIdx.y * 2;
    int b   = blockIdx.z;
    const float* f = frame + (size_t)b * H * W;

    // ---- prologue: weight convert (hi/lo fp16) + input window ----
    {
        __half* aH = (__half*)(smem + OFF_A_HI);
        __half* aL = (__half*)(smem + OFF_A_LO);
        for (int i = tid; i < 128 * 64; i += 256) {
            int ch = i >> 6, t = i & 63;
            float v = (t < 49) ? __ldg(wf + ch * 49 + t) : 0.f;
            __half h = __float2half_rn(v);
            aH[ch * BSTRIDE + t] = h;
            aL[ch * BSTRIDE + t] = __float2half_rn(v - __half2float(h));
        }
        int row0 = oy0 * 4 - 3, col0 = ox0 * 4 - 3;
        for (int i = tid; i < 11 * 131; i += 256) {
            int r = i / 131, c = i - r * 131;
            int y = row0 + r, x = col0 + c;
            s_in[r * 132 + c] = (y >= 0 && y < H && x >= 0 && x < W) ? f[(size_t)y * W + x] : 0.f;
        }
    }
    __syncthreads();

    // ---- im2col: 4 threads per px, 9 u32 words each ----
    {
        int px  = tid >> 2;
        int jq  = (tid & 3) * 9;
        u32* bB = (u32*)(smem + OFF_B) + px * 36;
        const float* base = s_in + (px >> 5) * 4 * 132 + (px & 31) * 4;
        #pragma unroll
        for (int jj = 0; jj < 9; jj++) {
            int j = jq + jj;
            int t0 = 2*j, t1 = 2*j + 1;
            float v0 = (t0 < 49) ? base[(t0/7) * 132 + (t0%7)] : 0.f;
            float v1 = (t1 < 49) ? base[(t1/7) * 132 + (t1%7)] : 0.f;
            bB[j] = pack_h2(v0, v1);
        }
    }
    __syncthreads();

    // ---- MMA main loop: warp = 16 ch x 64 px ----
    int m0 = warp * 16;
    float acc[8][4];
    #pragma unroll
    for (int ni = 0; ni < 8; ni++)
        #pragma unroll
        for (int r = 0; r < 4; r++) acc[ni][r] = 0.f;

    unsigned rowOff = ((lane & 15) * BSTRIDE + ((lane >> 4) << 3)) * 2;
    unsigned aHiBase = sbase + OFF_A_HI + m0 * (BSTRIDE*2) + rowOff;
    unsigned aLoBase = sbase + OFF_A_LO + m0 * (BSTRIDE*2) + rowOff;
    unsigned bBase   = sbase + OFF_B + rowOff;

    #pragma unroll
    for (int ks = 0; ks < 4; ks++) {
        unsigned kb = ks * 32;                      // 16 fp16 = 32 B
        u32 bb[8][2];
        #pragma unroll
        for (int nn = 0; nn < 4; nn++) {
            u32 r0, r1, r2, r3;
            LDM_X4(r0, r1, r2, r3, bBase + nn * 16 * (BSTRIDE*2) + kb);
            bb[2*nn][0]   = r0; bb[2*nn][1]   = r2;
            bb[2*nn+1][0] = r1; bb[2*nn+1][1] = r3;
        }
        {   // term hi
            u32 a0,a1,a2,a3;
            LDM_X4(a0,a1,a2,a3, aHiBase + kb);
            #pragma unroll
            for (int ni = 0; ni < 8; ni++)
                MMA16816F16(acc[ni], a0,a1,a2,a3, bb[ni][0], bb[ni][1]);
        }
        {   // term lo
            u32 a0,a1,a2,a3;
            LDM_X4(a0,a1,a2,a3, aLoBase + kb);
            #pragma unroll
            for (int ni = 0; ni < 8; ni++)
                MMA16816F16(acc[ni], a0,a1,a2,a3, bb[ni][0], bb[ni][1]);
        }
    }
    __syncthreads();   // A/B dead; stage overlays A

    // ---- epilogue: bias + relu -> conflict-free stage -> coalesced stores ----
    float* stg = (float*)smem;           // [px][132]
    {
        int ch0 = m0 + (lane >> 2);
        int ch1 = ch0 + 8;
        float bv0 = __ldg(bf + ch0);
        float bv1 = __ldg(bf + ch1);
        int pl = (lane & 3) * 2;
        #pragma unroll
        for (int ni = 0; ni < 8; ni++) {
            int px = ni * 8 + pl;
            stg[ px    * STG_STRIDE + ch0] = fmaxf(acc[ni][0] + bv0, 0.f);
            stg[(px+1) * STG_STRIDE + ch0] = fmaxf(acc[ni][1] + bv0, 0.f);
            stg[ px    * STG_STRIDE + ch1] = fmaxf(acc[ni][2] + bv1, 0.f);
            stg[(px+1) * STG_STRIDE + ch1] = fmaxf(acc[ni][3] + bv1, 0.f);
        }
    }
    __syncthreads();

    // fmap: [b][ch][oy][ox] — lanes = consecutive ox (coalesced 128B)
    for (int i = tid; i < 128 * 64; i += 256) {
        int px = i & 63, ch = i >> 6;
        int oy = oy0 + (px >> 5), ox = ox0 + (px & 31);
        fmap[(((size_t)(b*CH + ch))*OH + oy)*OW + ox] = stg[px * STG_STRIDE + ch];
    }
    // d_cl: [b][oy][ox][ch] — float4, coalesced 512B per warp
    for (int i = tid; i < 64 * 32; i += 256) {
        int px = i >> 5, c4 = (i & 31) * 4;
        float4 v = *(const float4*)(stg + px * STG_STRIDE + c4);
        int oy = oy0 + (px >> 5), ox = ox0 + (px & 31);
        *(float4*)(d_cl + (((size_t)(b*OH + oy))*OW + ox)*CH + c4) = v;
    }
}

// ================= K4: patches_f — channel-last coalesced gather =============
__global__ __launch_bounds__(128) void k_patches_f(float* __restrict__ out) {
    __shared__ float s[CH * 49];
    int bp = blockIdx.x;
    int b  = bp / NP;
    int c  = threadIdx.x;
    int xy = d_selxy[bp];
    float fx = (float)(xy & 0xFFFF) * 0.25f;
    float fy = (float)(xy >> 16)    * 0.25f;
    int x0 = (int)floorf(fx);
    int y0 = (int)floorf(fy);
    float wx = fx - (float)x0, wy = fy - (float)y0;
    int gx0 = x0 - 3, gy0 = y0 - 3;

    const float* base = d_cl + (size_t)b * OH * OW * CH + c;

    float v[64];
    #pragma unroll
    for (int pt = 0; pt < 64; pt++) {
        int yy = pt >> 3, xx = pt & 7;
        int gy = gy0 + yy, gx = gx0 + xx;
        bool ok = (gx >= 0) & (gx < OW) & (gy >= 0) & (gy < OH);
        v[pt] = ok ? __ldg(base + ((size_t)gy * OW + gx) * CH) : 0.f;
    }

    float w00 = (1.f - wx) * (1.f - wy);
    float w10 = wx * (1.f - wy);
    float w01 = (1.f - wx) * wy;
    float w11 = wx * wy;

    #pragma unroll
    for (int j = 0; j < 7; j++) {
        #pragma unroll
        for (int i = 0; i < 7; i++) {
            float acc = v[j*8 + i]       * w00
                      + v[j*8 + i + 1]   * w10
                      + v[(j+1)*8 + i]   * w01
                      + v[(j+1)*8 + i+1] * w11;
            s[c * 49 + (j*7 + i)] = acc;
        }
    }
    __syncthreads();

    float* o = out + (size_t)bp * (CH * 49);
    for (int k = threadIdx.x; k < CH * 49; k += 128)
        o[k] = s[k];
}

// ================= K5: patches_c — smem-staged weights =================
__global__ __launch_bounds__(128) void k_patches_c(
    const float* __restrict__ frame,
    const float* __restrict__ wc,
    const float* __restrict__ bc,
    float* __restrict__ out)
{
    __shared__ float s_w[CH * 49];
    __shared__ float s_in2[121];
    int bp = blockIdx.x;
    int b  = bp / NP;
    int c  = threadIdx.x;
    int xy = d_selxy[bp];
    float fx = (float)(xy & 0xFFFF) * 0.25f;
    float fy = (float)(xy >> 16)    * 0.25f;
    int x0 = (int)floorf(fx);
    int y0 = (int)floorf(fy);
    float wx = fx - (float)x0, wy = fy - (float)y0;

    const float* f = frame + (size_t)b * H * W;
    int row0 = y0 * 4 - 3, col0 = x0 * 4 - 3;
    for (int i = threadIdx.x; i < CH * 49; i += 128) s_w[i] = __ldg(wc + i);
    for (int i = threadIdx.x; i < 121; i += 128) {
        int r = i / 11, cc = i - r * 11;
        int yyy = row0 + r, xxx = col0 + cc;
        s_in2[i] = (yyy >= 0 && yyy < H && xxx >= 0 && xxx < W) ? f[yyy*W + xxx] : 0.f;
    }
    float bias = __ldg(bc + c);
    __syncthreads();

    float wreg[49];
    #pragma unroll
    for (int i = 0; i < 49; i++) wreg[i] = s_w[c*49 + i];

    float wts[4] = { (1.f-wx)*(1.f-wy), wx*(1.f-wy), (1.f-wx)*wy, wx*wy };
    float acc = 0.f;
    #pragma unroll
    for (int n = 0; n < 4; n++) {
        int dxn = n & 1, dyn = n >> 1;
        int xi = x0 + dxn, yi = y0 + dyn;
        if (xi < OW && yi < OH) {
            float v = bias;
            #pragma unroll
            for (int ky = 0; ky < 7; ky++)
                #pragma unroll
                for (int kx = 0; kx < 7; kx++)
                    v = fmaf(s_in2[(dyn*4 + ky)*11 + (dxn*4 + kx)], wreg[ky*7 + kx], v);
            v = fmaxf(v, 0.f);
            acc += v * wts[n];
        }
    }
    out[(size_t)bp * CH + c] = acc;
}

// ---------------- launch: fork-join; conv is the 4th launch ---------------------
extern "C" void kernel_launch(void* const* d_in, const int* in_sizes, int n_in,
                              void* d_out, int out_size) {
    const float* frame = (const float*)d_in[0];
    const float* w_f   = (const float*)d_in[1];
    const float* b_f   = (const float*)d_in[2];
    const float* w_c   = (const float*)d_in[3];
    const float* b_c   = (const float*)d_in[4];

    float* out        = (float*)d_out;
    float* out_coords = out;                                   // 8*192*2
    float* out_pf     = out + 3072;                            // 8*192*128*49
    float* out_pc     = out + 3072 + 9633792;                  // 8*192*128
    float* out_fmap   = out + 3072 + 9633792 + 196608;         // 8*128*120*160

    static cudaStream_t s1 = 0;
    static cudaEvent_t e_fork = 0, e_topk = 0, e_side = 0;
    if (!s1) {
        cudaStreamCreateWithFlags(&s1, cudaStreamNonBlocking);
        cudaEventCreateWithFlags(&e_fork, cudaEventDisableTiming);
        cudaEventCreateWithFlags(&e_topk, cudaEventDisableTiming);
        cudaEventCreateWithFlags(&e_side, cudaEventDisableTiming);
        cudaFuncSetAttribute(k_conv_tc, cudaFuncAttributeMaxDynamicSharedMemorySize, SMEM_TOT);
    }

    // fork
    cudaEventRecord(e_fork, 0);
    cudaStreamWaitEvent(s1, e_fork, 0);

    // side stream: harris -> topk -> patches_c (all before conv in submit order)
    k_harris<<<BN*256, 256, 0, s1>>>(frame);                     // launch 1
    k_topk  <<<BN, 256, 0, s1>>>(out_coords);                    // launch 2
    cudaEventRecord(e_topk, s1);
    k_patches_c<<<BN*NP, 128, 0, s1>>>(frame, w_c, b_c, out_pc); // launch 3
    cudaEventRecord(e_side, s1);

    // main stream: conv (4th launch -> ncu window) -> patches_f
    dim3 gconv(OW/32, OH/2, BN);
    k_conv_tc<<<gconv, 256, SMEM_TOT>>>(frame, w_f, b_f, out_fmap); // launch 4
    cudaStreamWaitEvent(0, e_topk, 0);
    k_patches_f<<<BN*NP, 128>>>(out_pf);                         // launch 5

    // join
    cudaStreamWaitEvent(0, e_side, 0);
}

// round 14
// speedup vs baseline: 1.3863x; 1.0352x over previous
#include <cuda_runtime.h>
#include <cuda_fp16.h>
#include <math.h>
#include <float.h>

#define BN 8
#define H 480
#define W 640
#define OH 120
#define OW 160
#define CH 128
#define NP 192

typedef unsigned long long u64;
typedef unsigned int u32;

// ---------------- scratch ----------------
__device__ float d_cellval[BN*256];
__device__ int   d_cellxy[BN*256];
__device__ int   d_selxy[BN*NP];
// channel-last fmap copy: [b][oy][ox][ch]
__device__ __align__(16) float d_cl[(size_t)BN*OH*OW*CH];
// paired fp16 hi/lo weights, layout-matched to conv smem: [ch][36] u32
__device__ u32 d_wAhi32[128*36];
__device__ u32 d_wAlo32[128*36];

// tap t -> s_in offset (row(t)*132 + col(t)); 0 for padding taps (masked)
__constant__ short c_off[64] = {
      0,  1,  2,  3,  4,  5,  6,
    132,133,134,135,136,137,138,
    264,265,266,267,268,269,270,
    396,397,398,399,400,401,402,
    528,529,530,531,532,533,534,
    660,661,662,663,664,665,666,
    792,793,794,795,796,797,798,
      0,  0,  0,  0,  0,  0,  0,  0,  0,  0,  0,  0,  0,  0,  0
};

// ---------------- helpers ----------------
__device__ __forceinline__ unsigned smem_u32(const void* p) {
    unsigned a;
    asm("{ .reg .u64 t; cvta.to.shared.u64 t, %1; cvt.u32.u64 %0, t; }" : "=r"(a) : "l"(p));
    return a;
}
#define LDM_X4(r0,r1,r2,r3,addr) \
    asm volatile("ldmatrix.sync.aligned.m8n8.x4.shared.b16 {%0,%1,%2,%3}, [%4];" \
        : "=r"(r0),"=r"(r1),"=r"(r2),"=r"(r3) : "r"(addr))
#define MMA16816F16(d, a0,a1,a2,a3, b0,b1) \
    asm volatile("mma.sync.aligned.m16n8k16.row.col.f32.f16.f16.f32 " \
        "{%0,%1,%2,%3}, {%4,%5,%6,%7}, {%8,%9}, {%0,%1,%2,%3};" \
        : "+f"((d)[0]),"+f"((d)[1]),"+f"((d)[2]),"+f"((d)[3]) \
        : "r"(a0),"r"(a1),"r"(a2),"r"(a3),"r"(b0),"r"(b1))

__device__ __forceinline__ u32 pack_h2(float v0, float v1) {
    __half2 h2 = __floats2half2_rn(v0, v1);
    return *(u32*)&h2;
}

// ================= K0: weight prep — fp16 hi/lo split, [ch][36] u32 =============
__global__ void k_wprep(const float* __restrict__ wf) {
    int i = blockIdx.x * blockDim.x + threadIdx.x;   // 128*36
    if (i >= 128*36) return;
    int ch = i / 36, j = i - ch*36;
    int t0 = 2*j, t1 = 2*j + 1;
    float v0 = (t0 < 49) ? __ldg(wf + ch*49 + t0) : 0.f;
    float v1 = (t1 < 49) ? __ldg(wf + ch*49 + t1) : 0.f;
    __half h0 = __float2half_rn(v0), h1 = __float2half_rn(v1);
    d_wAhi32[i] = pack_h2(__half2float(h0), __half2float(h1));
    d_wAlo32[i] = pack_h2(v0 - __half2float(h0), v1 - __half2float(h1));
}

// ================= K1: fused harris + per-cell argmax =================
__global__ __launch_bounds__(256) void k_harris(const float* __restrict__ frame) {
    __shared__ float sf[37][48];
    __shared__ float shxx[36][40], shyy[36][40], shxy[36][40];
    __shared__ float sv[256];
    __shared__ int   si[256];

    int blk = blockIdx.x;
    int b = blk >> 8, cell = blk & 255;
    int gh = cell >> 4, gw = cell & 15;
    int gx0 = gw * 40, gy0 = gh * 30;
    int X0 = gx0 - 3, Y0 = gy0 - 3;
    const float* f = frame + (size_t)b * H * W;
    int tid = threadIdx.x;

    for (int i = tid; i < 37 * 47; i += 256) {
        int r = i / 47, c = i - r * 47;
        int x = X0 + c, y = Y0 + r;
        sf[r][c] = (x >= 0 && x < W && y >= 0 && y < H) ? f[y * W + x] : 0.f;
    }
    __syncthreads();

    for (int i = tid; i < 36 * 40; i += 256) {
        int r = i / 40, c = i - r * 40;
        int y = Y0 + r;
        float a = 0.f, bb = 0.f, cc2 = 0.f;
        if (y >= 0 && y < H) {
            bool ylast = (y == H - 1);
            #pragma unroll
            for (int k = 0; k < 7; k++) {
                int cw = c + k;
                int x = X0 + cw;
                if (x >= 0 && x < W) {
                    float dx = (x < W - 1) ? (sf[r][cw+1] - sf[r][cw])
                                           : (sf[r][cw-1] - sf[r][cw-2]);
                    float dy = !ylast ? (sf[r+1][cw] - sf[r][cw])
                                      : (sf[r-1][cw] - sf[r-2][cw]);
                    a   = fmaf(dx, dx, a);
                    bb  = fmaf(dy, dy, bb);
                    cc2 = fmaf(dx, dy, cc2);
                }
            }
        }
        shxx[r][c] = a; shyy[r][c] = bb; shxy[r][c] = cc2;
    }
    __syncthreads();

    float bv = -FLT_MAX;
    int   bi = 0x7FFFFFFF;
    for (int fi = tid; fi < 1200; fi += 256) {
        int py = fi / 40, px = fi - py * 40;
        float a = 0.f, bb = 0.f, cc = 0.f;
        #pragma unroll
        for (int k = 0; k < 7; k++) {
            a  += shxx[py + k][px];
            bb += shyy[py + k][px];
            cc += shxy[py + k][px];
        }
        float Ixx = a / 49.0f, Iyy = bb / 49.0f, Ixy = cc / 49.0f;
        float g = (Ixx * Iyy - Ixy * Ixy) / (Ixx + Iyy + 1e-8f);
        if (g > bv) { bv = g; bi = fi; }
    }
    sv[tid] = bv; si[tid] = bi;
    __syncthreads();
    for (int s = 128; s > 0; s >>= 1) {
        if (tid < s) {
            float v2 = sv[tid + s]; int i2 = si[tid + s];
            if (v2 > sv[tid] || (v2 == sv[tid] && i2 < si[tid])) { sv[tid] = v2; si[tid] = i2; }
        }
        __syncthreads();
    }
    if (tid == 0) {
        int fi = si[0];
        int py = fi / 40, px = fi - py * 40;
        d_cellval[blk] = sv[0];
        d_cellxy[blk]  = ((gy0 + py) << 16) | (gx0 + px);
    }
}

// ================= K2: top-192 by rank count (stable) =================
__global__ void k_topk(float* __restrict__ out_coords) {
    __shared__ float sv[256];
    __shared__ int   sxy[256];
    int b = blockIdx.x, i = threadIdx.x;
    sv[i]  = d_cellval[b*256 + i];
    sxy[i] = d_cellxy[b*256 + i];
    __syncthreads();
    float v = sv[i];
    int rank = 0;
    #pragma unroll 8
    for (int j = 0; j < 256; j++) {
        float vj = sv[j];
        rank += (vj > v) || (vj == v && j < i);
    }
    if (rank < NP) {
        int xy = sxy[i];
        int x = xy & 0xFFFF, y = xy >> 16;
        out_coords[((size_t)b*NP + rank)*2 + 0] = (float)x;
        out_coords[((size_t)b*NP + rank)*2 + 1] = (float)y;
        d_selxy[b*NP + rank] = xy;
    }
}

// ================= K3: conv v14 — lean prologue, 3 blocks/SM =====================
// CTA: 256 thr = 8 warps, tile 2 oy x 32 ox = 64 px, 128 ch. Warp: 16 ch x 64 px.
// D = (Wh + Wl) . Xh^T, K padded 49->64, fp32 accum.
#define BSTRIDE 72                       // fp16 per row (144 B)
#define OFF_A_HI  0
#define OFF_A_LO  18432
#define OFF_B     36864                  // 64 rows x 144 B = 9216
#define OFF_IN    46080                  // float[11*132] = 5808 B
#define SMEM_TOT  51904
#define STG_STRIDE 132                   // stage overlays A: 64 px x 132 fl = 33792 B

__global__ __launch_bounds__(256, 3) void k_conv_tc(
    const float* __restrict__ frame,
    const float* __restrict__ bf,
    float* __restrict__ fmap)
{
    extern __shared__ __align__(16) unsigned char smem[];
    unsigned sbase = smem_u32(smem);
    float* s_in = (float*)(smem + OFF_IN);

    int tid  = threadIdx.x;
    int lane = tid & 31;
    int warp = tid >> 5;

    int ox0 = blockIdx.x * 32;
    int oy0 = blockIdx.y * 2;
    int b   = blockIdx.z;
    const float* f = frame + (size_t)b * H * W;

    // ---- prologue: coalesced paired-weight copy + input window ----
    {
        u32* aH = (u32*)(smem + OFF_A_HI);
        u32* aL = (u32*)(smem + OFF_A_LO);
        #pragma unroll
        for (int k = 0; k < 18; k++) {
            int i = k * 256 + tid;
            aH[i] = d_wAhi32[i];
            aL[i] = d_wAlo32[i];
        }
        int row0 = oy0 * 4 - 3, col0 = ox0 * 4 - 3;
        for (int i = tid; i < 11 * 131; i += 256) {
            int r = i / 131, c = i - r * 131;
            int y = row0 + r, x = col0 + c;
            s_in[r * 132 + c] = (y >= 0 && y < H && x >= 0 && x < W) ? f[(size_t)y * W + x] : 0.f;
        }
    }
    __syncthreads();

    // ---- im2col: 4 threads per px, 9 u32 words each; LUT offsets (no div) ----
    {
        int px  = tid >> 2;
        int jq  = (tid & 3) * 9;
        u32* bB = (u32*)(smem + OFF_B) + px * 36;
        const float* base = s_in + (px >> 5) * 4 * 132 + (px & 31) * 4;
        #pragma unroll
        for (int jj = 0; jj < 9; jj++) {
            int j = jq + jj;
            float v0 = (2*j     < 49) ? base[c_off[2*j]]     : 0.f;
            float v1 = (2*j + 1 < 49) ? base[c_off[2*j + 1]] : 0.f;
            bB[j] = pack_h2(v0, v1);
        }
    }
    __syncthreads();

    // ---- MMA main loop: warp = 16 ch x 64 px ----
    int m0 = warp * 16;
    float acc[8][4];
    #pragma unroll
    for (int ni = 0; ni < 8; ni++)
        #pragma unroll
        for (int r = 0; r < 4; r++) acc[ni][r] = 0.f;

    unsigned rowOff = ((lane & 15) * BSTRIDE + ((lane >> 4) << 3)) * 2;
    unsigned aHiBase = sbase + OFF_A_HI + m0 * (BSTRIDE*2) + rowOff;
    unsigned aLoBase = sbase + OFF_A_LO + m0 * (BSTRIDE*2) + rowOff;
    unsigned bBase   = sbase + OFF_B + rowOff;

    #pragma unroll
    for (int ks = 0; ks < 4; ks++) {
        unsigned kb = ks * 32;                      // 16 fp16 = 32 B
        u32 bb[8][2];
        #pragma unroll
        for (int nn = 0; nn < 4; nn++) {
            u32 r0, r1, r2, r3;
            LDM_X4(r0, r1, r2, r3, bBase + nn * 16 * (BSTRIDE*2) + kb);
            bb[2*nn][0]   = r0; bb[2*nn][1]   = r2;
            bb[2*nn+1][0] = r1; bb[2*nn+1][1] = r3;
        }
        {   // term hi
            u32 a0,a1,a2,a3;
            LDM_X4(a0,a1,a2,a3, aHiBase + kb);
            #pragma unroll
            for (int ni = 0; ni < 8; ni++)
                MMA16816F16(acc[ni], a0,a1,a2,a3, bb[ni][0], bb[ni][1]);
        }
        {   // term lo
            u32 a0,a1,a2,a3;
            LDM_X4(a0,a1,a2,a3, aLoBase + kb);
            #pragma unroll
            for (int ni = 0; ni < 8; ni++)
                MMA16816F16(acc[ni], a0,a1,a2,a3, bb[ni][0], bb[ni][1]);
        }
    }
    __syncthreads();   // A/B dead; stage overlays A

    // ---- epilogue: bias + relu -> conflict-free stage -> coalesced stores ----
    float* stg = (float*)smem;           // [px][132]
    {
        int ch0 = m0 + (lane >> 2);
        int ch1 = ch0 + 8;
        float bv0 = __ldg(bf + ch0);
        float bv1 = __ldg(bf + ch1);
        int pl = (lane & 3) * 2;
        #pragma unroll
        for (int ni = 0; ni < 8; ni++) {
            int px = ni * 8 + pl;
            stg[ px    * STG_STRIDE + ch0] = fmaxf(acc[ni][0] + bv0, 0.f);
            stg[(px+1) * STG_STRIDE + ch0] = fmaxf(acc[ni][1] + bv0, 0.f);
            stg[ px    * STG_STRIDE + ch1] = fmaxf(acc[ni][2] + bv1, 0.f);
            stg[(px+1) * STG_STRIDE + ch1] = fmaxf(acc[ni][3] + bv1, 0.f);
        }
    }
    __syncthreads();

    // fmap: [b][ch][oy][ox] — lanes = consecutive ox (coalesced 128B)
    for (int i = tid; i < 128 * 64; i += 256) {
        int px = i & 63, ch = i >> 6;
        int oy = oy0 + (px >> 5), ox = ox0 + (px & 31);
        fmap[(((size_t)(b*CH + ch))*OH + oy)*OW + ox] = stg[px * STG_STRIDE + ch];
    }
    // d_cl: [b][oy][ox][ch] — float4, coalesced 512B per warp
    for (int i = tid; i < 64 * 32; i += 256) {
        int px = i >> 5, c4 = (i & 31) * 4;
        float4 v = *(const float4*)(stg + px * STG_STRIDE + c4);
        int oy = oy0 + (px >> 5), ox = ox0 + (px & 31);
        *(float4*)(d_cl + (((size_t)(b*OH + oy))*OW + ox)*CH + c4) = v;
    }
}

// ================= K4: patches_f — channel-last coalesced gather =============
__global__ __launch_bounds__(128) void k_patches_f(float* __restrict__ out) {
    __shared__ float s[CH * 49];
    int bp = blockIdx.x;
    int b  = bp / NP;
    int c  = threadIdx.x;
    int xy = d_selxy[bp];
    float fx = (float)(xy & 0xFFFF) * 0.25f;
    float fy = (float)(xy >> 16)    * 0.25f;
    int x0 = (int)floorf(fx);
    int y0 = (int)floorf(fy);
    float wx = fx - (float)x0, wy = fy - (float)y0;
    int gx0 = x0 - 3, gy0 = y0 - 3;

    const float* base = d_cl + (size_t)b * OH * OW * CH + c;

    float v[64];
    #pragma unroll
    for (int pt = 0; pt < 64; pt++) {
        int yy = pt >> 3, xx = pt & 7;
        int gy = gy0 + yy, gx = gx0 + xx;
        bool ok = (gx >= 0) & (gx < OW) & (gy >= 0) & (gy < OH);
        v[pt] = ok ? __ldg(base + ((size_t)gy * OW + gx) * CH) : 0.f;
    }

    float w00 = (1.f - wx) * (1.f - wy);
    float w10 = wx * (1.f - wy);
    float w01 = (1.f - wx) * wy;
    float w11 = wx * wy;

    #pragma unroll
    for (int j = 0; j < 7; j++) {
        #pragma unroll
        for (int i = 0; i < 7; i++) {
            float acc = v[j*8 + i]       * w00
                      + v[j*8 + i + 1]   * w10
                      + v[(j+1)*8 + i]   * w01
                      + v[(j+1)*8 + i+1] * w11;
            s[c * 49 + (j*7 + i)] = acc;
        }
    }
    __syncthreads();

    float* o = out + (size_t)bp * (CH * 49);
    for (int k = threadIdx.x; k < CH * 49; k += 128)
        o[k] = s[k];
}

// ================= K5: patches_c — smem-staged weights =================
__global__ __launch_bounds__(128) void k_patches_c(
    const float* __restrict__ frame,
    const float* __restrict__ wc,
    const float* __restrict__ bc,
    float* __restrict__ out)
{
    __shared__ float s_w[CH * 49];
    __shared__ float s_in2[121];
    int bp = blockIdx.x;
    int b  = bp / NP;
    int c  = threadIdx.x;
    int xy = d_selxy[bp];
    float fx = (float)(xy & 0xFFFF) * 0.25f;
    float fy = (float)(xy >> 16)    * 0.25f;
    int x0 = (int)floorf(fx);
    int y0 = (int)floorf(fy);
    float wx = fx - (float)x0, wy = fy - (float)y0;

    const float* f = frame + (size_t)b * H * W;
    int row0 = y0 * 4 - 3, col0 = x0 * 4 - 3;
    for (int i = threadIdx.x; i < CH * 49; i += 128) s_w[i] = __ldg(wc + i);
    for (int i = threadIdx.x; i < 121; i += 128) {
        int r = i / 11, cc = i - r * 11;
        int yyy = row0 + r, xxx = col0 + cc;
        s_in2[i] = (yyy >= 0 && yyy < H && xxx >= 0 && xxx < W) ? f[yyy*W + xxx] : 0.f;
    }
    float bias = __ldg(bc + c);
    __syncthreads();

    float wreg[49];
    #pragma unroll
    for (int i = 0; i < 49; i++) wreg[i] = s_w[c*49 + i];

    float wts[4] = { (1.f-wx)*(1.f-wy), wx*(1.f-wy), (1.f-wx)*wy, wx*wy };
    float acc = 0.f;
    #pragma unroll
    for (int n = 0; n < 4; n++) {
        int dxn = n & 1, dyn = n >> 1;
        int xi = x0 + dxn, yi = y0 + dyn;
        if (xi < OW && yi < OH) {
            float v = bias;
            #pragma unroll
            for (int ky = 0; ky < 7; ky++)
                #pragma unroll
                for (int kx = 0; kx < 7; kx++)
                    v = fmaf(s_in2[(dyn*4 + ky)*11 + (dxn*4 + kx)], wreg[ky*7 + kx], v);
            v = fmaxf(v, 0.f);
            acc += v * wts[n];
        }
    }
    out[(size_t)bp * CH + c] = acc;
}

// ---------------- launch: fork-join; conv is the 4th launch ---------------------
extern "C" void kernel_launch(void* const* d_in, const int* in_sizes, int n_in,
                              void* d_out, int out_size) {
    const float* frame = (const float*)d_in[0];
    const float* w_f   = (const float*)d_in[1];
    const float* b_f   = (const float*)d_in[2];
    const float* w_c   = (const float*)d_in[3];
    const float* b_c   = (const float*)d_in[4];

    float* out        = (float*)d_out;
    float* out_coords = out;                                   // 8*192*2
    float* out_pf     = out + 3072;                            // 8*192*128*49
    float* out_pc     = out + 3072 + 9633792;                  // 8*192*128
    float* out_fmap   = out + 3072 + 9633792 + 196608;         // 8*128*120*160

    static cudaStream_t s1 = 0;
    static cudaEvent_t e_fork = 0, e_topk = 0, e_side = 0;
    if (!s1) {
        cudaStreamCreateWithFlags(&s1, cudaStreamNonBlocking);
        cudaEventCreateWithFlags(&e_fork, cudaEventDisableTiming);
        cudaEventCreateWithFlags(&e_topk, cudaEventDisableTiming);
        cudaEventCreateWithFlags(&e_side, cudaEventDisableTiming);
        cudaFuncSetAttribute(k_conv_tc, cudaFuncAttributeMaxDynamicSharedMemorySize, SMEM_TOT);
    }

    // fork
    cudaEventRecord(e_fork, 0);
    cudaStreamWaitEvent(s1, e_fork, 0);

    // side stream part 1: harris -> topk
    k_harris<<<BN*256, 256, 0, s1>>>(frame);                     // launch 1
    k_topk  <<<BN, 256, 0, s1>>>(out_coords);                    // launch 2
    cudaEventRecord(e_topk, s1);

    // main stream: wprep (3rd) -> conv (4th, ncu window)
    k_wprep<<<36, 128>>>(w_f);                                   // launch 3
    dim3 gconv(OW/32, OH/2, BN);
    k_conv_tc<<<gconv, 256, SMEM_TOT>>>(frame, b_f, out_fmap);   // launch 4

    // side stream part 2: patches_c
    k_patches_c<<<BN*NP, 128, 0, s1>>>(frame, w_c, b_c, out_pc); // launch 5
    cudaEventRecord(e_side, s1);

    // main stream: patches_f (needs conv output AND topk coords)
    cudaStreamWaitEvent(0, e_topk, 0);
    k_patches_f<<<BN*NP, 128>>>(out_pf);                         // launch 6

    // join
    cudaStreamWaitEvent(0, e_side, 0);
}

// round 15
// speedup vs baseline: 1.4557x; 1.0501x over previous
#include <cuda_runtime.h>
#include <cuda_fp16.h>
#include <math.h>
#include <float.h>

#define BN 8
#define H 480
#define W 640
#define OH 120
#define OW 160
#define CH 128
#define NP 192

typedef unsigned long long u64;
typedef unsigned int u32;

// ---------------- scratch ----------------
__device__ float d_cellval[BN*256];
__device__ int   d_cellxy[BN*256];
__device__ int   d_selxy[BN*NP];
// channel-last fmap copy: [b][oy][ox][ch]
__device__ __align__(16) float d_cl[(size_t)BN*OH*OW*CH];

// tap t -> s_in offset (row(t)*132 + col(t)); 0 for padding taps (masked)
__constant__ short c_off[64] = {
      0,  1,  2,  3,  4,  5,  6,
    132,133,134,135,136,137,138,
    264,265,266,267,268,269,270,
    396,397,398,399,400,401,402,
    528,529,530,531,532,533,534,
    660,661,662,663,664,665,666,
    792,793,794,795,796,797,798,
      0,  0,  0,  0,  0,  0,  0,  0,  0,  0,  0,  0,  0,  0,  0
};

// ---------------- helpers ----------------
__device__ __forceinline__ unsigned smem_u32(const void* p) {
    unsigned a;
    asm("{ .reg .u64 t; cvta.to.shared.u64 t, %1; cvt.u32.u64 %0, t; }" : "=r"(a) : "l"(p));
    return a;
}
#define LDM_X4(r0,r1,r2,r3,addr) \
    asm volatile("ldmatrix.sync.aligned.m8n8.x4.shared.b16 {%0,%1,%2,%3}, [%4];" \
        : "=r"(r0),"=r"(r1),"=r"(r2),"=r"(r3) : "r"(addr))
#define MMA16816F16(d, a0,a1,a2,a3, b0,b1) \
    asm volatile("mma.sync.aligned.m16n8k16.row.col.f32.f16.f16.f32 " \
        "{%0,%1,%2,%3}, {%4,%5,%6,%7}, {%8,%9}, {%0,%1,%2,%3};" \
        : "+f"((d)[0]),"+f"((d)[1]),"+f"((d)[2]),"+f"((d)[3]) \
        : "r"(a0),"r"(a1),"r"(a2),"r"(a3),"r"(b0),"r"(b1))

__device__ __forceinline__ u32 pack_h2(float v0, float v1) {
    __half2 h2 = __floats2half2_rn(v0, v1);
    return *(u32*)&h2;
}

// ================= K1: fused harris + per-cell argmax =================
__global__ __launch_bounds__(256) void k_harris(const float* __restrict__ frame) {
    __shared__ float sf[37][48];
    __shared__ float shxx[36][40], shyy[36][40], shxy[36][40];
    __shared__ float sv[256];
    __shared__ int   si[256];

    int blk = blockIdx.x;
    int b = blk >> 8, cell = blk & 255;
    int gh = cell >> 4, gw = cell & 15;
    int gx0 = gw * 40, gy0 = gh * 30;
    int X0 = gx0 - 3, Y0 = gy0 - 3;
    const float* f = frame + (size_t)b * H * W;
    int tid = threadIdx.x;

    for (int i = tid; i < 37 * 47; i += 256) {
        int r = i / 47, c = i - r * 47;
        int x = X0 + c, y = Y0 + r;
        sf[r][c] = (x >= 0 && x < W && y >= 0 && y < H) ? f[y * W + x] : 0.f;
    }
    __syncthreads();

    for (int i = tid; i < 36 * 40; i += 256) {
        int r = i / 40, c = i - r * 40;
        int y = Y0 + r;
        float a = 0.f, bb = 0.f, cc2 = 0.f;
        if (y >= 0 && y < H) {
            bool ylast = (y == H - 1);
            #pragma unroll
            for (int k = 0; k < 7; k++) {
                int cw = c + k;
                int x = X0 + cw;
                if (x >= 0 && x < W) {
                    float dx = (x < W - 1) ? (sf[r][cw+1] - sf[r][cw])
                                           : (sf[r][cw-1] - sf[r][cw-2]);
                    float dy = !ylast ? (sf[r+1][cw] - sf[r][cw])
                                      : (sf[r-1][cw] - sf[r-2][cw]);
                    a   = fmaf(dx, dx, a);
                    bb  = fmaf(dy, dy, bb);
                    cc2 = fmaf(dx, dy, cc2);
                }
            }
        }
        shxx[r][c] = a; shyy[r][c] = bb; shxy[r][c] = cc2;
    }
    __syncthreads();

    float bv = -FLT_MAX;
    int   bi = 0x7FFFFFFF;
    for (int fi = tid; fi < 1200; fi += 256) {
        int py = fi / 40, px = fi - py * 40;
        float a = 0.f, bb = 0.f, cc = 0.f;
        #pragma unroll
        for (int k = 0; k < 7; k++) {
            a  += shxx[py + k][px];
            bb += shyy[py + k][px];
            cc += shxy[py + k][px];
        }
        float Ixx = a / 49.0f, Iyy = bb / 49.0f, Ixy = cc / 49.0f;
        float g = (Ixx * Iyy - Ixy * Ixy) / (Ixx + Iyy + 1e-8f);
        if (g > bv) { bv = g; bi = fi; }
    }
    sv[tid] = bv; si[tid] = bi;
    __syncthreads();
    for (int s = 128; s > 0; s >>= 1) {
        if (tid < s) {
            float v2 = sv[tid + s]; int i2 = si[tid + s];
            if (v2 > sv[tid] || (v2 == sv[tid] && i2 < si[tid])) { sv[tid] = v2; si[tid] = i2; }
        }
        __syncthreads();
    }
    if (tid == 0) {
        int fi = si[0];
        int py = fi / 40, px = fi - py * 40;
        d_cellval[blk] = sv[0];
        d_cellxy[blk]  = ((gy0 + py) << 16) | (gx0 + px);
    }
}

// ================= K2: top-192 by rank count (stable) =================
__global__ void k_topk(float* __restrict__ out_coords) {
    __shared__ float sv[256];
    __shared__ int   sxy[256];
    int b = blockIdx.x, i = threadIdx.x;
    sv[i]  = d_cellval[b*256 + i];
    sxy[i] = d_cellxy[b*256 + i];
    __syncthreads();
    float v = sv[i];
    int rank = 0;
    #pragma unroll 8
    for (int j = 0; j < 256; j++) {
        float vj = sv[j];
        rank += (vj > v) || (vj == v && j < i);
    }
    if (rank < NP) {
        int xy = sxy[i];
        int x = xy & 0xFFFF, y = xy >> 16;
        out_coords[((size_t)b*NP + rank)*2 + 0] = (float)x;
        out_coords[((size_t)b*NP + rank)*2 + 1] = (float)y;
        d_selxy[b*NP + rank] = xy;
    }
}

// ================= K3: conv v15 — persistent blocks, weights loaded once ========
// Grid 444 (3/SM), grid-stride over 2400 tiles (2 oy x 32 ox x 8 b).
// Warp: 16 ch x 64 px. D = (Wh + Wl) . Xh^T, K padded 49->64.
#define BSTRIDE 72                       // fp16 per row (144 B)
#define NTILES  2400
#define OFF_A_HI  0                      // 18432
#define OFF_A_LO  18432                  // 18432
#define OFF_U     36864                  // union: B(9216)+IN(5808) | STAGE(16896)
#define OFF_B     OFF_U
#define OFF_IN    (OFF_U + 9216)
#define SMEM_TOT  53760
#define STG_STRIDE 132                   // stage: 32 px x 132 floats = 16896 B

__global__ __launch_bounds__(256, 3) void k_conv_tc(
    const float* __restrict__ frame,
    const float* __restrict__ wf,
    const float* __restrict__ bf,
    float* __restrict__ fmap)
{
    extern __shared__ __align__(16) unsigned char smem[];
    unsigned sbase = smem_u32(smem);
    float* s_in = (float*)(smem + OFF_IN);
    float* stg  = (float*)(smem + OFF_U);

    int tid  = threadIdx.x;
    int lane = tid & 31;
    int warp = tid >> 5;

    // ---- once per block: weight convert fp32 -> fp16 hi/lo into smem ----
    {
        u32* aH = (u32*)(smem + OFF_A_HI);
        u32* aL = (u32*)(smem + OFF_A_LO);
        #pragma unroll
        for (int k = 0; k < 18; k++) {
            int i = k * 256 + tid;              // 4608 u32 entries
            int ch = i / 36, j = i - ch * 36;
            int t0 = 2*j, t1 = 2*j + 1;
            float v0 = (t0 < 49) ? __ldg(wf + ch*49 + t0) : 0.f;
            float v1 = (t1 < 49) ? __ldg(wf + ch*49 + t1) : 0.f;
            __half h0 = __float2half_rn(v0), h1 = __float2half_rn(v1);
            aH[ch*36 + j] = pack_h2(__half2float(h0), __half2float(h1));
            aL[ch*36 + j] = pack_h2(v0 - __half2float(h0), v1 - __half2float(h1));
        }
    }

    // per-warp constants
    int m0  = warp * 16;
    int ch0 = m0 + (lane >> 2);
    int ch1 = ch0 + 8;
    float bv0 = __ldg(bf + ch0);
    float bv1 = __ldg(bf + ch1);
    int pl = (lane & 3) * 2;
    unsigned rowOff  = ((lane & 15) * BSTRIDE + ((lane >> 4) << 3)) * 2;
    unsigned aHiBase = sbase + OFF_A_HI + m0 * (BSTRIDE*2) + rowOff;
    unsigned aLoBase = sbase + OFF_A_LO + m0 * (BSTRIDE*2) + rowOff;
    unsigned bBase   = sbase + OFF_B + rowOff;

    // ---- persistent tile loop ----
    for (int t = blockIdx.x; t < NTILES; t += gridDim.x) {
        int b  = t / 300;
        int r  = t - b * 300;
        int ty = r / 5;
        int tx = r - ty * 5;
        int oy0 = ty * 2, ox0 = tx * 32;
        const float* f = frame + (size_t)b * H * W;

        __syncthreads();    // union region free (previous tile's stage reads done)

        // input window 11 x 131
        {
            int row0 = oy0 * 4 - 3, col0 = ox0 * 4 - 3;
            for (int i = tid; i < 11 * 131; i += 256) {
                int rr = i / 131, cc = i - rr * 131;
                int y = row0 + rr, x = col0 + cc;
                s_in[rr * 132 + cc] = (y >= 0 && y < H && x >= 0 && x < W)
                                      ? f[(size_t)y * W + x] : 0.f;
            }
        }
        __syncthreads();

        // im2col: 4 threads per px, 9 u32 words each
        {
            int px = tid >> 2;
            int jq = (tid & 3) * 9;
            u32* bB = (u32*)(smem + OFF_B) + px * 36;
            const float* base = s_in + (px >> 5) * 4 * 132 + (px & 31) * 4;
            #pragma unroll
            for (int jj = 0; jj < 9; jj++) {
                int j = jq + jj;
                float v0 = (2*j     < 49) ? base[c_off[2*j]]     : 0.f;
                float v1 = (2*j + 1 < 49) ? base[c_off[2*j + 1]] : 0.f;
                bB[j] = pack_h2(v0, v1);
            }
        }
        __syncthreads();

        // MMA: warp = 16 ch x 64 px
        float acc[8][4];
        #pragma unroll
        for (int ni = 0; ni < 8; ni++)
            #pragma unroll
            for (int rr = 0; rr < 4; rr++) acc[ni][rr] = 0.f;

        #pragma unroll
        for (int ks = 0; ks < 4; ks++) {
            unsigned kb = ks * 32;
            u32 bb[8][2];
            #pragma unroll
            for (int nn = 0; nn < 4; nn++) {
                u32 r0, r1, r2, r3;
                LDM_X4(r0, r1, r2, r3, bBase + nn * 16 * (BSTRIDE*2) + kb);
                bb[2*nn][0]   = r0; bb[2*nn][1]   = r2;
                bb[2*nn+1][0] = r1; bb[2*nn+1][1] = r3;
            }
            {   // term hi
                u32 a0,a1,a2,a3;
                LDM_X4(a0,a1,a2,a3, aHiBase + kb);
                #pragma unroll
                for (int ni = 0; ni < 8; ni++)
                    MMA16816F16(acc[ni], a0,a1,a2,a3, bb[ni][0], bb[ni][1]);
            }
            {   // term lo
                u32 a0,a1,a2,a3;
                LDM_X4(a0,a1,a2,a3, aLoBase + kb);
                #pragma unroll
                for (int ni = 0; ni < 8; ni++)
                    MMA16816F16(acc[ni], a0,a1,a2,a3, bb[ni][0], bb[ni][1]);
            }
        }

        // epilogue: 2 passes of 32 px (one oy row each); stage overlays B/IN
        #pragma unroll
        for (int p = 0; p < 2; p++) {
            __syncthreads();    // B/IN (or previous stage) reads done
            #pragma unroll
            for (int nq = 0; nq < 4; nq++) {
                int ni = p * 4 + nq;
                int pxl = nq * 8 + pl;      // 0..31 within this pass
                stg[ pxl    * STG_STRIDE + ch0] = fmaxf(acc[ni][0] + bv0, 0.f);
                stg[(pxl+1) * STG_STRIDE + ch0] = fmaxf(acc[ni][1] + bv0, 0.f);
                stg[ pxl    * STG_STRIDE + ch1] = fmaxf(acc[ni][2] + bv1, 0.f);
                stg[(pxl+1) * STG_STRIDE + ch1] = fmaxf(acc[ni][3] + bv1, 0.f);
            }
            __syncthreads();

            int oy = oy0 + p;
            // fmap: [b][ch][oy][ox] — lanes = consecutive ox (coalesced 128B)
            for (int i = tid; i < 128 * 32; i += 256) {
                int pxl = i & 31, ch = i >> 5;
                fmap[(((size_t)(b*CH + ch))*OH + oy)*OW + ox0 + pxl] =
                    stg[pxl * STG_STRIDE + ch];
            }
            // d_cl: [b][oy][ox][ch] — float4, coalesced
            for (int i = tid; i < 32 * 32; i += 256) {
                int pxl = i >> 5, c4 = (i & 31) * 4;
                float4 v = *(const float4*)(stg + pxl * STG_STRIDE + c4);
                *(float4*)(d_cl + (((size_t)(b*OH + oy))*OW + ox0 + pxl)*CH + c4) = v;
            }
        }
    }
}

// ================= K4: patches_f — channel-last coalesced gather =============
__global__ __launch_bounds__(128) void k_patches_f(float* __restrict__ out) {
    __shared__ float s[CH * 49];
    int bp = blockIdx.x;
    int b  = bp / NP;
    int c  = threadIdx.x;
    int xy = d_selxy[bp];
    float fx = (float)(xy & 0xFFFF) * 0.25f;
    float fy = (float)(xy >> 16)    * 0.25f;
    int x0 = (int)floorf(fx);
    int y0 = (int)floorf(fy);
    float wx = fx - (float)x0, wy = fy - (float)y0;
    int gx0 = x0 - 3, gy0 = y0 - 3;

    const float* base = d_cl + (size_t)b * OH * OW * CH + c;

    float v[64];
    #pragma unroll
    for (int pt = 0; pt < 64; pt++) {
        int yy = pt >> 3, xx = pt & 7;
        int gy = gy0 + yy, gx = gx0 + xx;
        bool ok = (gx >= 0) & (gx < OW) & (gy >= 0) & (gy < OH);
        v[pt] = ok ? __ldg(base + ((size_t)gy * OW + gx) * CH) : 0.f;
    }

    float w00 = (1.f - wx) * (1.f - wy);
    float w10 = wx * (1.f - wy);
    float w01 = (1.f - wx) * wy;
    float w11 = wx * wy;

    #pragma unroll
    for (int j = 0; j < 7; j++) {
        #pragma unroll
        for (int i = 0; i < 7; i++) {
            float acc = v[j*8 + i]       * w00
                      + v[j*8 + i + 1]   * w10
                      + v[(j+1)*8 + i]   * w01
                      + v[(j+1)*8 + i+1] * w11;
            s[c * 49 + (j*7 + i)] = acc;
        }
    }
    __syncthreads();

    float* o = out + (size_t)bp * (CH * 49);
    for (int k = threadIdx.x; k < CH * 49; k += 128)
        o[k] = s[k];
}

// ================= K5: patches_c — smem-staged weights =================
__global__ __launch_bounds__(128) void k_patches_c(
    const float* __restrict__ frame,
    const float* __restrict__ wc,
    const float* __restrict__ bc,
    float* __restrict__ out)
{
    __shared__ float s_w[CH * 49];
    __shared__ float s_in2[121];
    int bp = blockIdx.x;
    int b  = bp / NP;
    int c  = threadIdx.x;
    int xy = d_selxy[bp];
    float fx = (float)(xy & 0xFFFF) * 0.25f;
    float fy = (float)(xy >> 16)    * 0.25f;
    int x0 = (int)floorf(fx);
    int y0 = (int)floorf(fy);
    float wx = fx - (float)x0, wy = fy - (float)y0;

    const float* f = frame + (size_t)b * H * W;
    int row0 = y0 * 4 - 3, col0 = x0 * 4 - 3;
    for (int i = threadIdx.x; i < CH * 49; i += 128) s_w[i] = __ldg(wc + i);
    for (int i = threadIdx.x; i < 121; i += 128) {
        int r = i / 11, cc = i - r * 11;
        int yyy = row0 + r, xxx = col0 + cc;
        s_in2[i] = (yyy >= 0 && yyy < H && xxx >= 0 && xxx < W) ? f[yyy*W + xxx] : 0.f;
    }
    float bias = __ldg(bc + c);
    __syncthreads();

    float wreg[49];
    #pragma unroll
    for (int i = 0; i < 49; i++) wreg[i] = s_w[c*49 + i];

    float wts[4] = { (1.f-wx)*(1.f-wy), wx*(1.f-wy), (1.f-wx)*wy, wx*wy };
    float acc = 0.f;
    #pragma unroll
    for (int n = 0; n < 4; n++) {
        int dxn = n & 1, dyn = n >> 1;
        int xi = x0 + dxn, yi = y0 + dyn;
        if (xi < OW && yi < OH) {
            float v = bias;
            #pragma unroll
            for (int ky = 0; ky < 7; ky++)
                #pragma unroll
                for (int kx = 0; kx < 7; kx++)
                    v = fmaf(s_in2[(dyn*4 + ky)*11 + (dxn*4 + kx)], wreg[ky*7 + kx], v);
            v = fmaxf(v, 0.f);
            acc += v * wts[n];
        }
    }
    out[(size_t)bp * CH + c] = acc;
}

// ---------------- launch: conv is the 4th submission (ncu window) ---------------
extern "C" void kernel_launch(void* const* d_in, const int* in_sizes, int n_in,
                              void* d_out, int out_size) {
    const float* frame = (const float*)d_in[0];
    const float* w_f   = (const float*)d_in[1];
    const float* b_f   = (const float*)d_in[2];
    const float* w_c   = (const float*)d_in[3];
    const float* b_c   = (const float*)d_in[4];

    float* out        = (float*)d_out;
    float* out_coords = out;                                   // 8*192*2
    float* out_pf     = out + 3072;                            // 8*192*128*49
    float* out_pc     = out + 3072 + 9633792;                  // 8*192*128
    float* out_fmap   = out + 3072 + 9633792 + 196608;         // 8*128*120*160

    static cudaStream_t s1 = 0;
    static cudaEvent_t e_fork = 0, e_topk = 0, e_side = 0;
    if (!s1) {
        cudaStreamCreateWithFlags(&s1, cudaStreamNonBlocking);
        cudaEventCreateWithFlags(&e_fork, cudaEventDisableTiming);
        cudaEventCreateWithFlags(&e_topk, cudaEventDisableTiming);
        cudaEventCreateWithFlags(&e_side, cudaEventDisableTiming);
        cudaFuncSetAttribute(k_conv_tc, cudaFuncAttributeMaxDynamicSharedMemorySize, SMEM_TOT);
    }

    // fork
    cudaEventRecord(e_fork, 0);
    cudaStreamWaitEvent(s1, e_fork, 0);

    // side stream: harris -> topk -> patches_c
    k_harris<<<BN*256, 256, 0, s1>>>(frame);                     // launch 1
    k_topk  <<<BN, 256, 0, s1>>>(out_coords);                    // launch 2
    cudaEventRecord(e_topk, s1);
    k_patches_c<<<BN*NP, 128, 0, s1>>>(frame, w_c, b_c, out_pc); // launch 3
    cudaEventRecord(e_side, s1);

    // main stream: conv (4th submission) -> patches_f
    k_conv_tc<<<444, 256, SMEM_TOT>>>(frame, w_f, b_f, out_fmap); // launch 4
    cudaStreamWaitEvent(0, e_topk, 0);
    k_patches_f<<<BN*NP, 128>>>(out_pf);                          // launch 5

    // join
    cudaStreamWaitEvent(0, e_side, 0);
}